// round 5
// baseline (speedup 1.0000x reference)
#include <cuda_runtime.h>
#include <cuda_bf16.h>
#include <cstdint>

#define N 8192
#define BITS 16
#define NLAB 81
#define GAMMA 0.5f
#define ETA 0.5f

#define TILE 128
#define GRID_X (N / TILE)            // 64
#define GRID_Y (N / TILE)            // 64
#define NCTA (GRID_X * GRID_Y)       // 4096
#define ROWS_PER_BLOCK 16
#define NPROLOG (N / ROWS_PER_BLOCK) // 512

// c = 0.5*log2(e): accumulate c*theta so softplus(theta/2) = ln2*log2(1+exp2(c*theta))
#define CSCALE  0.72134752044448170368f
#define LN2F    0.69314718055994530942f
#define TWO_LN2 1.38629436111989061884f
#define SCALE35 2.91038304567337036133e-11f   /* 2^-35 */

typedef unsigned long long u64;

// ---- device scratch ----
__device__ __nv_bfloat16 g_Fb[N * BITS];   // bf16(CSCALE * F)
__device__ __nv_bfloat16 g_Gb[N * BITS];   // bf16(G)
__device__ uint4  g_imgp[N];               // packed labels {b0-31,b32-63,b64-80,0}
__device__ uint4  g_texp[N];
__device__ float  g_colF[NPROLOG * BITS];  // per-block column sums of F
__device__ float  g_colG[NPROLOG * BITS];
__device__ double g_partial[NCTA];
__device__ double g_partial2[NPROLOG];

__device__ __forceinline__ uint32_t smem_u32(const void* p) {
    uint32_t a;
    asm("{ .reg .u64 t; cvta.to.shared.u64 t, %1; cvt.u32.u64 %0, t; }" : "=r"(a) : "l"(p));
    return a;
}
#define EX2(d, s) asm("ex2.approx.f32 %0, %1;" : "=f"(d) : "f"(s))
#define LG2(d, s) asm("lg2.approx.f32 %0, %1;" : "=f"(d) : "f"(s))

#define LDSM_X4(r0, r1, r2, r3, addr) \
    asm volatile("ldmatrix.sync.aligned.m8n8.x4.shared.b16 {%0,%1,%2,%3}, [%4];" \
                 : "=r"(r0), "=r"(r1), "=r"(r2), "=r"(r3) : "r"(addr))

__device__ __forceinline__ void mma16816(float& d0, float& d1, float& d2, float& d3,
                                         uint32_t a0, uint32_t a1, uint32_t a2, uint32_t a3,
                                         uint32_t b0, uint32_t b1) {
    asm volatile(
        "mma.sync.aligned.m16n8k16.row.col.f32.bf16.bf16.f32 "
        "{%0,%1,%2,%3}, {%4,%5,%6,%7}, {%8,%9}, {%10,%11,%12,%13};"
        : "=f"(d0), "=f"(d1), "=f"(d2), "=f"(d3)
        : "r"(a0), "r"(a1), "r"(a2), "r"(a3), "r"(b0), "r"(b1),
          "f"(0.0f), "f"(0.0f), "f"(0.0f), "f"(0.0f));
}

__device__ __forceinline__ uint32_t fold3(uint4 a, uint4 b) {
    return (a.x & b.x) | (a.y & b.y) | (a.z & b.z);
}

// ---------------------------------------------------------------------------
// Prolog: 16 rows per block, 2 rows per warp (high MLP). Ballot-packs labels,
// emits bf16(c*F)/bf16(G), per-block term2/term3 partials, and per-block
// column sums of F and G (for the global sum(theta) identity).
// ---------------------------------------------------------------------------
__global__ __launch_bounds__(256)
void prolog_kernel(const int* __restrict__ img, const int* __restrict__ tex,
                   const float* __restrict__ F, const float* __restrict__ G,
                   const float* __restrict__ Bq) {
    __shared__ float sColF[128], sColG[128], sT23[16];

    const int w    = threadIdx.x >> 5;
    const int lane = threadIdx.x & 31;
    const int rowA = blockIdx.x * ROWS_PER_BLOCK + w * 2;
    const int rowB = rowA + 1;
    const int half = lane >> 4;
    const int k    = lane & 15;
    const int row  = rowA + half;

    // ---- labels: all loads issued up front (MLP=12) ----
    const int* irA = img + (long long)rowA * NLAB;
    const int* irB = img + (long long)rowB * NLAB;
    const int* trA = tex + (long long)rowA * NLAB;
    const int* trB = tex + (long long)rowB * NLAB;
    int a0v = irA[lane], a1v = irA[32 + lane], a2v = (lane < NLAB - 64) ? irA[64 + lane] : 0;
    int b0v = irB[lane], b1v = irB[32 + lane], b2v = (lane < NLAB - 64) ? irB[64 + lane] : 0;
    int c0v = trA[lane], c1v = trA[32 + lane], c2v = (lane < NLAB - 64) ? trA[64 + lane] : 0;
    int d0v = trB[lane], d1v = trB[32 + lane], d2v = (lane < NLAB - 64) ? trB[64 + lane] : 0;

    float f = F[(long long)row * BITS + k];
    float g = G[(long long)row * BITS + k];
    float b = Bq[(long long)row * BITS + k];

    unsigned iA0 = __ballot_sync(0xffffffffu, a0v != 0);
    unsigned iA1 = __ballot_sync(0xffffffffu, a1v != 0);
    unsigned iA2 = __ballot_sync(0xffffffffu, a2v != 0);
    unsigned iB0 = __ballot_sync(0xffffffffu, b0v != 0);
    unsigned iB1 = __ballot_sync(0xffffffffu, b1v != 0);
    unsigned iB2 = __ballot_sync(0xffffffffu, b2v != 0);
    unsigned tA0 = __ballot_sync(0xffffffffu, c0v != 0);
    unsigned tA1 = __ballot_sync(0xffffffffu, c1v != 0);
    unsigned tA2 = __ballot_sync(0xffffffffu, c2v != 0);
    unsigned tB0 = __ballot_sync(0xffffffffu, d0v != 0);
    unsigned tB1 = __ballot_sync(0xffffffffu, d1v != 0);
    unsigned tB2 = __ballot_sync(0xffffffffu, d2v != 0);
    if (lane == 0) {
        g_imgp[rowA] = make_uint4(iA0, iA1, iA2, 0u);
        g_imgp[rowB] = make_uint4(iB0, iB1, iB2, 0u);
        g_texp[rowA] = make_uint4(tA0, tA1, tA2, 0u);
        g_texp[rowB] = make_uint4(tB0, tB1, tB2, 0u);
    }

    // bf16 conversions (contiguous 64B per warp across the 2 rows)
    g_Fb[(long long)row * BITS + k] = __float2bfloat16_rn(f * CSCALE);
    g_Gb[(long long)row * BITS + k] = __float2bfloat16_rn(g);

    // term2/term3: reduce within each 16-lane half (one row each)
    float df = b - f, dg = b - g;
    float q  = df * df + dg * dg;
    float sf = f, sg = g;
#pragma unroll
    for (int off = 8; off > 0; off >>= 1) {
        q  += __shfl_xor_sync(0xffffffffu, q,  off);
        sf += __shfl_xor_sync(0xffffffffu, sf, off);
        sg += __shfl_xor_sync(0xffffffffu, sg, off);
    }
    if (k == 0)
        sT23[w * 2 + half] = GAMMA * q + ETA * (sf * sf + sg * sg);

    // column sums of the warp's 2 rows: lane k gets F[rowA,k]+F[rowB,k]
    float fc = f + __shfl_xor_sync(0xffffffffu, f, 16);
    float gc = g + __shfl_xor_sync(0xffffffffu, g, 16);
    if (half == 0) {
        sColF[w * 16 + k] = fc;
        sColG[w * 16 + k] = gc;
    }
    __syncthreads();

    if (threadIdx.x < 16) {
        float cf = 0.0f, cg = 0.0f;
#pragma unroll
        for (int ww = 0; ww < 8; ww++) {
            cf += sColF[ww * 16 + threadIdx.x];
            cg += sColG[ww * 16 + threadIdx.x];
        }
        g_colF[blockIdx.x * BITS + threadIdx.x] = cf;
        g_colG[blockIdx.x * BITS + threadIdx.x] = cg;
    }
    if (threadIdx.x == 0) {
        float s = 0.0f;
#pragma unroll
        for (int i = 0; i < 16; i++) s += sT23[i];
        g_partial2[blockIdx.x] = (double)s;
    }
}

// ---------------------------------------------------------------------------
// Main: 128x128 c*theta tile per CTA via mma.sync bf16. Epilogue accumulates
// softplus in log2 domain (1 lg2 per 8 via scaled product-of-8) and only
// DETECTS non-sim pairs (umin tree); the masked theta sum is reconstructed
// globally as sum_all(theta) - sum_nonsim(theta), where sum_nonsim comes from
// a fallback pass that statistically never runs.
// ---------------------------------------------------------------------------
__global__ __launch_bounds__(256)
void theta_loss_kernel() {
    __shared__ __nv_bfloat16 sA[TILE * BITS];
    __shared__ __nv_bfloat16 sB[TILE * BITS];
    __shared__ uint4 sIlab[TILE];
    __shared__ uint4 sTlab[TILE];
    __shared__ float warp_sum[8];

    const int tid  = threadIdx.x;
    const int wid  = tid >> 5;
    const int lane = tid & 31;
    const int i0   = blockIdx.y * TILE;
    const int t0   = blockIdx.x * TILE;

    {
        const int r = tid >> 1;
        const int h = (tid & 1) * 8;
        *(uint4*)(sA + r * BITS + h) = *(const uint4*)(g_Fb + (long long)(i0 + r) * BITS + h);
        *(uint4*)(sB + r * BITS + h) = *(const uint4*)(g_Gb + (long long)(t0 + r) * BITS + h);
    }
    if (tid < TILE) sIlab[tid] = g_imgp[i0 + tid];
    else            sTlab[tid - TILE] = g_texp[t0 + (tid - TILE)];
    __syncthreads();

    const int rbase = wid * 16;
    uint32_t a0, a1, a2, a3;
    {
        uint32_t addr = smem_u32(sA) + (uint32_t)((rbase + (lane & 15)) * 32 + ((lane >> 4) << 4));
        LDSM_X4(a0, a1, a2, a3, addr);
    }

    const uint32_t sBu = smem_u32(sB);
    const int qc = (lane & 3) * 2;
    const uint4 il_lo = sIlab[rbase + (lane >> 2)];
    const uint4 il_hi = sIlab[rbase + (lane >> 2) + 8];

    float lsum = 0.0f;
    uint32_t rmin = 0xffffffffu;

#pragma unroll
    for (int it = 0; it < 8; it++) {
        const int n0 = it * 16;
        uint32_t b0, b1, b2, b3;
        {
            uint32_t addr = sBu + (uint32_t)((n0 + (lane & 7) + ((lane >> 4) << 3)) * 32
                                             + (((lane >> 3) & 1) << 4));
            LDSM_X4(b0, b1, b2, b3, addr);
        }

        float d0, d1, d2, d3, e0, e1, e2, e3;
        mma16816(d0, d1, d2, d3, a0, a1, a2, a3, b0, b1);
        mma16816(e0, e1, e2, e3, a0, a1, a2, a3, b2, b3);

        // softplus(log2 domain): one lg2 per 8 elements via scaled product
        float x0, x1, x2, x3, y0, y1, y2, y3;
        EX2(x0, d0); EX2(x1, d1); EX2(x2, d2); EX2(x3, d3);
        EX2(y0, e0); EX2(y1, e1); EX2(y2, e2); EX2(y3, e3);
        float f01 = fmaf(x0, x1, x0 + x1);           // (1+x0)(1+x1)-1
        float f23 = fmaf(x2, x3, x2 + x3);
        float qx  = fmaf(f01, f23, f01 + f23) + 1.0f;
        float g01 = fmaf(y0, y1, y0 + y1);
        float g23 = fmaf(y2, y3, y2 + y3);
        float qy  = fmaf(g01, g23, g01 + g23) + 1.0f;
        float prod = (qx * SCALE35) * (qy * SCALE35);   // in [2^-70, 2^74]
        float lp;
        LG2(lp, prod);
        lsum += lp;                                      // true value - 70

        // nonsim DETECTION only (w==0 <=> no shared label)
        const uint4 ta = sTlab[n0 + qc];
        const uint4 tb = sTlab[n0 + qc + 1];
        const uint4 tc = sTlab[n0 + qc + 8];
        const uint4 td = sTlab[n0 + qc + 9];
        uint32_t w0 = fold3(il_lo, ta), w1 = fold3(il_lo, tb);
        uint32_t w2 = fold3(il_hi, ta), w3 = fold3(il_hi, tb);
        uint32_t w4 = fold3(il_lo, tc), w5 = fold3(il_lo, td);
        uint32_t w6 = fold3(il_hi, tc), w7 = fold3(il_hi, td);
        uint32_t m01 = min(w0, w1), m23 = min(w2, w3);
        uint32_t m45 = min(w4, w5), m67 = min(w6, w7);
        rmin = min(rmin, min(min(m01, m23), min(m45, m67)));
    }

    float corr = 0.0f;  // sum of c*theta over genuinely non-sim pairs (≈ never)
    if (__ballot_sync(0xffffffffu, rmin == 0u)) {
#pragma unroll 1
        for (int it = 0; it < 8; it++) {
            const int n0 = it * 16;
            uint32_t b0, b1, b2, b3;
            uint32_t addr = sBu + (uint32_t)((n0 + (lane & 7) + ((lane >> 4) << 3)) * 32
                                             + (((lane >> 3) & 1) << 4));
            LDSM_X4(b0, b1, b2, b3, addr);
            float d0, d1, d2, d3, e0, e1, e2, e3;
            mma16816(d0, d1, d2, d3, a0, a1, a2, a3, b0, b1);
            mma16816(e0, e1, e2, e3, a0, a1, a2, a3, b2, b3);
            const uint4 ta = sTlab[n0 + qc];
            const uint4 tb = sTlab[n0 + qc + 1];
            const uint4 tc = sTlab[n0 + qc + 8];
            const uint4 td = sTlab[n0 + qc + 9];
            if (fold3(il_lo, ta) == 0u) corr += d0;
            if (fold3(il_lo, tb) == 0u) corr += d1;
            if (fold3(il_hi, ta) == 0u) corr += d2;
            if (fold3(il_hi, tb) == 0u) corr += d3;
            if (fold3(il_lo, tc) == 0u) corr += e0;
            if (fold3(il_lo, td) == 0u) corr += e1;
            if (fold3(il_hi, tc) == 0u) corr += e2;
            if (fold3(il_hi, td) == 0u) corr += e3;
        }
    }

    // +560 = 8 iterations * 70 (scale restore)
    float sum = LN2F * (lsum + 560.0f) + TWO_LN2 * corr;
#pragma unroll
    for (int off = 16; off > 0; off >>= 1)
        sum += __shfl_down_sync(0xffffffffu, sum, off);
    if (lane == 0) warp_sum[wid] = sum;
    __syncthreads();
    if (tid == 0) {
        float s = 0.0f;
#pragma unroll
        for (int w = 0; w < 8; w++) s += warp_sum[w];
        g_partial[blockIdx.y * gridDim.x + blockIdx.x] = (double)s;
    }
}

// ---------------------------------------------------------------------------
// Finalize: fixed-order sum of all partials, minus sum_all(theta) computed
// from the exact f32 column sums:  sum_theta = sum_k SF_k * SG_k.
// ---------------------------------------------------------------------------
__global__ void finalize_kernel(float* __restrict__ out) {
    __shared__ double sh[256];
    __shared__ double sSF[256], sSG[256];
    __shared__ double sTh[16];
    const int t = threadIdx.x;

    double acc = 0.0;
    for (int p = t; p < NCTA; p += 256) acc += g_partial[p];
    for (int p = t; p < NPROLOG; p += 256) acc += g_partial2[p];

    // column sums: thread (c = t>>4, k = t&15) covers blocks [c*32, c*32+32)
    {
        const int k = t & 15;
        const int c = t >> 4;
        double pf = 0.0, pg = 0.0;
        for (int b = c * 32; b < c * 32 + 32; b++) {
            pf += (double)g_colF[b * BITS + k];
            pg += (double)g_colG[b * BITS + k];
        }
        sSF[t] = pf;
        sSG[t] = pg;
    }
    __syncthreads();
    if (t < 16) {
        double sf = 0.0, sg = 0.0;
#pragma unroll
        for (int c = 0; c < 16; c++) {
            sf += sSF[c * 16 + t];
            sg += sSG[c * 16 + t];
        }
        sTh[t] = sf * sg;
    }
    __syncthreads();

    sh[t] = acc;
    __syncthreads();
    for (int s = 128; s > 0; s >>= 1) {
        if (t < s) sh[t] += sh[t + s];
        __syncthreads();
    }
    if (t == 0) {
        double th = 0.0;
#pragma unroll
        for (int k = 0; k < 16; k++) th += sTh[k];
        out[0] = (float)(sh[0] - th);
    }
}

// ---------------------------------------------------------------------------
extern "C" void kernel_launch(void* const* d_in, const int* in_sizes, int n_in,
                              void* d_out, int out_size) {
    const float* F = (const float*)d_in[0];
    const float* G = (const float*)d_in[1];
    const float* B = (const float*)d_in[2];
    const int* img = (const int*)d_in[3];
    const int* tex = (const int*)d_in[4];
    float* out = (float*)d_out;

    prolog_kernel<<<NPROLOG, 256>>>(img, tex, F, G, B);

    dim3 grid(GRID_X, GRID_Y);
    theta_loss_kernel<<<grid, 256>>>();

    finalize_kernel<<<1, 256>>>(out);
}

// round 6
// speedup vs baseline: 1.0604x; 1.0604x over previous
#include <cuda_runtime.h>
#include <cuda_bf16.h>
#include <cstdint>

#define N 8192
#define BITS 16
#define NLAB 81
#define GAMMA 0.5f
#define ETA 0.5f

#define TILE 128
#define GRID_X (N / TILE)            // 64
#define GRID_Y (N / TILE)            // 64
#define NCTA (GRID_X * GRID_Y)       // 4096
#define ROWS_PER_BLOCK 16
#define NPROLOG (N / ROWS_PER_BLOCK) // 512

// c = 0.5*log2(e): accumulate c*theta so softplus(theta/2) = ln2*log2(1+exp2(c*theta))
#define CSCALE  0.72134752044448170368f
#define LN2F    0.69314718055994530942f
#define TWO_LN2 1.38629436111989061884f
#define SCALE35 2.91038304567337036133e-11f   /* 2^-35 */

typedef unsigned long long u64;

// ---- device scratch ----
__device__ __nv_bfloat16 g_Fb[N * BITS];   // bf16(CSCALE * F)
__device__ __nv_bfloat16 g_Gb[N * BITS];   // bf16(G)
__device__ uint4  g_imgp[N];               // packed labels {b0-31,b32-63,b64-80,0}
__device__ uint4  g_texp[N];
__device__ float  g_colF[NPROLOG * BITS];  // per-block column sums of F
__device__ float  g_colG[NPROLOG * BITS];
__device__ double g_partial[NCTA];
__device__ double g_partial2[NPROLOG];

__device__ __forceinline__ uint32_t smem_u32(const void* p) {
    uint32_t a;
    asm("{ .reg .u64 t; cvta.to.shared.u64 t, %1; cvt.u32.u64 %0, t; }" : "=r"(a) : "l"(p));
    return a;
}
#define EX2(d, s) asm("ex2.approx.f32 %0, %1;" : "=f"(d) : "f"(s))
#define LG2(d, s) asm("lg2.approx.f32 %0, %1;" : "=f"(d) : "f"(s))

#define LDSM_X4(r0, r1, r2, r3, addr) \
    asm volatile("ldmatrix.sync.aligned.m8n8.x4.shared.b16 {%0,%1,%2,%3}, [%4];" \
                 : "=r"(r0), "=r"(r1), "=r"(r2), "=r"(r3) : "r"(addr))

__device__ __forceinline__ void mma16816(float& d0, float& d1, float& d2, float& d3,
                                         uint32_t a0, uint32_t a1, uint32_t a2, uint32_t a3,
                                         uint32_t b0, uint32_t b1) {
    asm volatile(
        "mma.sync.aligned.m16n8k16.row.col.f32.bf16.bf16.f32 "
        "{%0,%1,%2,%3}, {%4,%5,%6,%7}, {%8,%9}, {%10,%11,%12,%13};"
        : "=f"(d0), "=f"(d1), "=f"(d2), "=f"(d3)
        : "r"(a0), "r"(a1), "r"(a2), "r"(a3), "r"(b0), "r"(b1),
          "f"(0.0f), "f"(0.0f), "f"(0.0f), "f"(0.0f));
}

__device__ __forceinline__ uint32_t fold3(uint4 a, uint4 b) {
    return (a.x & b.x) | (a.y & b.y) | (a.z & b.z);
}

// ---------------------------------------------------------------------------
// Prolog: 16 rows per block, 2 rows per warp. Ballot-packs labels, emits
// bf16(c*F)/bf16(G), term2/term3 partials, per-block column sums of F,G.
// ---------------------------------------------------------------------------
__global__ __launch_bounds__(256)
void prolog_kernel(const int* __restrict__ img, const int* __restrict__ tex,
                   const float* __restrict__ F, const float* __restrict__ G,
                   const float* __restrict__ Bq) {
    __shared__ float sColF[128], sColG[128], sT23[16];

    const int w    = threadIdx.x >> 5;
    const int lane = threadIdx.x & 31;
    const int rowA = blockIdx.x * ROWS_PER_BLOCK + w * 2;
    const int rowB = rowA + 1;
    const int half = lane >> 4;
    const int k    = lane & 15;
    const int row  = rowA + half;

    const int* irA = img + (long long)rowA * NLAB;
    const int* irB = img + (long long)rowB * NLAB;
    const int* trA = tex + (long long)rowA * NLAB;
    const int* trB = tex + (long long)rowB * NLAB;
    int a0v = irA[lane], a1v = irA[32 + lane], a2v = (lane < NLAB - 64) ? irA[64 + lane] : 0;
    int b0v = irB[lane], b1v = irB[32 + lane], b2v = (lane < NLAB - 64) ? irB[64 + lane] : 0;
    int c0v = trA[lane], c1v = trA[32 + lane], c2v = (lane < NLAB - 64) ? trA[64 + lane] : 0;
    int d0v = trB[lane], d1v = trB[32 + lane], d2v = (lane < NLAB - 64) ? trB[64 + lane] : 0;

    float f = F[(long long)row * BITS + k];
    float g = G[(long long)row * BITS + k];
    float b = Bq[(long long)row * BITS + k];

    unsigned iA0 = __ballot_sync(0xffffffffu, a0v != 0);
    unsigned iA1 = __ballot_sync(0xffffffffu, a1v != 0);
    unsigned iA2 = __ballot_sync(0xffffffffu, a2v != 0);
    unsigned iB0 = __ballot_sync(0xffffffffu, b0v != 0);
    unsigned iB1 = __ballot_sync(0xffffffffu, b1v != 0);
    unsigned iB2 = __ballot_sync(0xffffffffu, b2v != 0);
    unsigned tA0 = __ballot_sync(0xffffffffu, c0v != 0);
    unsigned tA1 = __ballot_sync(0xffffffffu, c1v != 0);
    unsigned tA2 = __ballot_sync(0xffffffffu, c2v != 0);
    unsigned tB0 = __ballot_sync(0xffffffffu, d0v != 0);
    unsigned tB1 = __ballot_sync(0xffffffffu, d1v != 0);
    unsigned tB2 = __ballot_sync(0xffffffffu, d2v != 0);
    if (lane == 0) {
        g_imgp[rowA] = make_uint4(iA0, iA1, iA2, 0u);
        g_imgp[rowB] = make_uint4(iB0, iB1, iB2, 0u);
        g_texp[rowA] = make_uint4(tA0, tA1, tA2, 0u);
        g_texp[rowB] = make_uint4(tB0, tB1, tB2, 0u);
    }

    g_Fb[(long long)row * BITS + k] = __float2bfloat16_rn(f * CSCALE);
    g_Gb[(long long)row * BITS + k] = __float2bfloat16_rn(g);

    float df = b - f, dg = b - g;
    float q  = df * df + dg * dg;
    float sf = f, sg = g;
#pragma unroll
    for (int off = 8; off > 0; off >>= 1) {
        q  += __shfl_xor_sync(0xffffffffu, q,  off);
        sf += __shfl_xor_sync(0xffffffffu, sf, off);
        sg += __shfl_xor_sync(0xffffffffu, sg, off);
    }
    if (k == 0)
        sT23[w * 2 + half] = GAMMA * q + ETA * (sf * sf + sg * sg);

    float fc = f + __shfl_xor_sync(0xffffffffu, f, 16);
    float gc = g + __shfl_xor_sync(0xffffffffu, g, 16);
    if (half == 0) {
        sColF[w * 16 + k] = fc;
        sColG[w * 16 + k] = gc;
    }
    __syncthreads();

    if (threadIdx.x < 16) {
        float cf = 0.0f, cg = 0.0f;
#pragma unroll
        for (int ww = 0; ww < 8; ww++) {
            cf += sColF[ww * 16 + threadIdx.x];
            cg += sColG[ww * 16 + threadIdx.x];
        }
        g_colF[blockIdx.x * BITS + threadIdx.x] = cf;
        g_colG[blockIdx.x * BITS + threadIdx.x] = cg;
    }
    if (threadIdx.x == 0) {
        float s = 0.0f;
#pragma unroll
        for (int i = 0; i < 16; i++) s += sT23[i];
        g_partial2[blockIdx.x] = (double)s;
    }
}

// ---------------------------------------------------------------------------
// Main: 128x128 c*theta tile per CTA via mma.sync bf16. Softplus in log2
// domain (1 lg2 / 8 elems). Sim handling: Σ_sim θ = Σθ − Σ_nonsim θ, where
// Σθ comes from exact column sums (finalize). Non-sim pairs are caught by a
// 32-bit word0 pre-filter (P≈1e-4/elem); a warp-uniform rare branch does the
// exact 81-bit check IN PLACE on the live accumulators.
// ---------------------------------------------------------------------------
__global__ __launch_bounds__(256, 4)
void theta_loss_kernel() {
    __shared__ __nv_bfloat16 sA[TILE * BITS];
    __shared__ __nv_bfloat16 sB[TILE * BITS];
    __shared__ uint32_t sIx[TILE];     // img label word0
    __shared__ uint32_t sTx[TILE];     // tex label word0
    __shared__ uint4 sIfull[TILE];     // full 81-bit labels (rare path)
    __shared__ uint4 sTfull[TILE];
    __shared__ float warp_sum[8];

    const int tid  = threadIdx.x;
    const int wid  = tid >> 5;
    const int lane = tid & 31;
    const int i0   = blockIdx.y * TILE;
    const int t0   = blockIdx.x * TILE;

    {
        const int r = tid >> 1;
        const int h = (tid & 1) * 8;
        *(uint4*)(sA + r * BITS + h) = *(const uint4*)(g_Fb + (long long)(i0 + r) * BITS + h);
        *(uint4*)(sB + r * BITS + h) = *(const uint4*)(g_Gb + (long long)(t0 + r) * BITS + h);
    }
    if (tid < TILE) {
        uint4 v = g_imgp[i0 + tid];
        sIfull[tid] = v;
        sIx[tid] = v.x;
    } else {
        uint4 v = g_texp[t0 + (tid - TILE)];
        sTfull[tid - TILE] = v;
        sTx[tid - TILE] = v.x;
    }
    __syncthreads();

    const int rbase = wid * 16;
    uint32_t a0, a1, a2, a3;
    {
        uint32_t addr = smem_u32(sA) + (uint32_t)((rbase + (lane & 15)) * 32 + ((lane >> 4) << 4));
        LDSM_X4(a0, a1, a2, a3, addr);
    }

    const uint32_t sBu = smem_u32(sB);
    const int qc = (lane & 3) * 2;
    const int rlo = rbase + (lane >> 2);
    const int rhi = rlo + 8;
    const uint32_t il0 = sIx[rlo];
    const uint32_t il8 = sIx[rhi];

    float lsum = 0.0f;
    float corr = 0.0f;   // Σ c*theta over genuinely non-sim pairs (rare)

#pragma unroll
    for (int it = 0; it < 8; it++) {
        const int n0 = it * 16;
        uint32_t b0, b1, b2, b3;
        {
            uint32_t addr = sBu + (uint32_t)((n0 + (lane & 7) + ((lane >> 4) << 3)) * 32
                                             + (((lane >> 3) & 1) << 4));
            LDSM_X4(b0, b1, b2, b3, addr);
        }

        float d0, d1, d2, d3, e0, e1, e2, e3;
        mma16816(d0, d1, d2, d3, a0, a1, a2, a3, b0, b1);
        mma16816(e0, e1, e2, e3, a0, a1, a2, a3, b2, b3);

        // softplus in log2 domain: one lg2 per 8 elements (scaled product)
        float x0, x1, x2, x3, y0, y1, y2, y3;
        EX2(x0, d0); EX2(x1, d1); EX2(x2, d2); EX2(x3, d3);
        EX2(y0, e0); EX2(y1, e1); EX2(y2, e2); EX2(y3, e3);
        float f01 = fmaf(x0, x1, x0 + x1);
        float f23 = fmaf(x2, x3, x2 + x3);
        float qx  = fmaf(f01, f23, f01 + f23) + 1.0f;
        float g01 = fmaf(y0, y1, y0 + y1);
        float g23 = fmaf(y2, y3, y2 + y3);
        float qy  = fmaf(g01, g23, g01 + g23) + 1.0f;
        float prod = (qx * SCALE35) * (qy * SCALE35);   // [2^-70, 2^74]
        float lp;
        LG2(lp, prod);
        lsum += lp;                                      // true value - 70

        // word0 pre-filter
        const uint32_t taX = sTx[n0 + qc];
        const uint32_t tbX = sTx[n0 + qc + 1];
        const uint32_t tcX = sTx[n0 + qc + 8];
        const uint32_t tdX = sTx[n0 + qc + 9];
        uint32_t w0 = il0 & taX, w1 = il0 & tbX, w2 = il8 & taX, w3 = il8 & tbX;
        uint32_t w4 = il0 & tcX, w5 = il0 & tdX, w6 = il8 & tcX, w7 = il8 & tdX;
        uint32_t m8 = min(min(min(w0, w1), min(w2, w3)), min(min(w4, w5), min(w6, w7)));

        if (__any_sync(0xffffffffu, m8 == 0u)) {   // rare (~2.5% of warp-iters)
            const uint4 IL = sIfull[rlo];
            const uint4 IH = sIfull[rhi];
            const uint4 TA = sTfull[n0 + qc];
            const uint4 TB = sTfull[n0 + qc + 1];
            const uint4 TC = sTfull[n0 + qc + 8];
            const uint4 TD = sTfull[n0 + qc + 9];
            if (fold3(IL, TA) == 0u) corr += d0;
            if (fold3(IL, TB) == 0u) corr += d1;
            if (fold3(IH, TA) == 0u) corr += d2;
            if (fold3(IH, TB) == 0u) corr += d3;
            if (fold3(IL, TC) == 0u) corr += e0;
            if (fold3(IL, TD) == 0u) corr += e1;
            if (fold3(IH, TC) == 0u) corr += e2;
            if (fold3(IH, TD) == 0u) corr += e3;
        }
    }

    // +560 = 8 iterations * 70 (scale restore). corr converts c*theta -> theta.
    float sum = LN2F * (lsum + 560.0f) + TWO_LN2 * corr;
#pragma unroll
    for (int off = 16; off > 0; off >>= 1)
        sum += __shfl_down_sync(0xffffffffu, sum, off);
    if (lane == 0) warp_sum[wid] = sum;
    __syncthreads();
    if (tid == 0) {
        float s = 0.0f;
#pragma unroll
        for (int w = 0; w < 8; w++) s += warp_sum[w];
        g_partial[blockIdx.y * gridDim.x + blockIdx.x] = (double)s;
    }
}

// ---------------------------------------------------------------------------
// Finalize: fixed-order sum of all partials minus Σθ = Σ_k SF_k * SG_k.
// ---------------------------------------------------------------------------
__global__ void finalize_kernel(float* __restrict__ out) {
    __shared__ double sh[256];
    __shared__ double sSF[256], sSG[256];
    __shared__ double sTh[16];
    const int t = threadIdx.x;

    double acc = 0.0;
    for (int p = t; p < NCTA; p += 256) acc += g_partial[p];
    for (int p = t; p < NPROLOG; p += 256) acc += g_partial2[p];

    {
        const int k = t & 15;
        const int c = t >> 4;
        double pf = 0.0, pg = 0.0;
        for (int b = c * 32; b < c * 32 + 32; b++) {
            pf += (double)g_colF[b * BITS + k];
            pg += (double)g_colG[b * BITS + k];
        }
        sSF[t] = pf;
        sSG[t] = pg;
    }
    __syncthreads();
    if (t < 16) {
        double sf = 0.0, sg = 0.0;
#pragma unroll
        for (int c = 0; c < 16; c++) {
            sf += sSF[c * 16 + t];
            sg += sSG[c * 16 + t];
        }
        sTh[t] = sf * sg;
    }
    __syncthreads();

    sh[t] = acc;
    __syncthreads();
    for (int s = 128; s > 0; s >>= 1) {
        if (t < s) sh[t] += sh[t + s];
        __syncthreads();
    }
    if (t == 0) {
        double th = 0.0;
#pragma unroll
        for (int k = 0; k < 16; k++) th += sTh[k];
        out[0] = (float)(sh[0] - th);
    }
}

// ---------------------------------------------------------------------------
extern "C" void kernel_launch(void* const* d_in, const int* in_sizes, int n_in,
                              void* d_out, int out_size) {
    const float* F = (const float*)d_in[0];
    const float* G = (const float*)d_in[1];
    const float* B = (const float*)d_in[2];
    const int* img = (const int*)d_in[3];
    const int* tex = (const int*)d_in[4];
    float* out = (float*)d_out;

    prolog_kernel<<<NPROLOG, 256>>>(img, tex, F, G, B);

    dim3 grid(GRID_X, GRID_Y);
    theta_loss_kernel<<<grid, 256>>>();

    finalize_kernel<<<1, 256>>>(out);
}